// round 2
// baseline (speedup 1.0000x reference)
#include <cuda_runtime.h>
#include <math.h>
#include <stdint.h>

#define TPB 256
#define NEGF -1000000000.0f

// Scratch (allocation-free rule: __device__ globals).
__device__ float g_loss[256];
__device__ float g_logZ[64 * 1000];

// ---------------------------------------------------------------------------
// Phase 1: logZ[b][t] = log( exp(-1) + sum_{u=0..tl-1} exp(x[b,t,u]) )
// One warp per (b,t) row. Fully parallel, memory-bound.
// ---------------------------------------------------------------------------
__global__ void __launch_bounds__(TPB)
fsloss_logz(const float* __restrict__ attn,
            const int* __restrict__ text_lens,
            int B, int T, int U)
{
    int gw   = (blockIdx.x * blockDim.x + threadIdx.x) >> 5;
    int lane = threadIdx.x & 31;
    if (gw >= B * T) return;
    int b = gw / T;
    int tl = text_lens[b];

    const float* row = attn + (size_t)gw * (size_t)U;
    float s = 0.0f;
    for (int c = lane; c < tl; c += 32)
        s += __expf(__ldg(&row[c]));
    #pragma unroll
    for (int off = 16; off; off >>= 1)
        s += __shfl_xor_sync(0xffffffffu, s, off);
    if (lane == 0)
        g_logZ[gw] = __logf(s + 0.36787944117144233f);  // + exp(-1) blank
}

// ---------------------------------------------------------------------------
// Phase 2: per-batch CTC forward scan in LOG DOMAIN (mirrors reference
// arithmetic: lse with max-subtraction, new = lp + (m + log(sum))).
// One CTA per batch element; 256 threads handle 512 states (2 each);
// ONE barrier per time step via double buffering.
// ---------------------------------------------------------------------------
__global__ void __launch_bounds__(TPB)
fsloss_scan(const float* __restrict__ attn,
            const int* __restrict__ text_lens,
            const int* __restrict__ mel_lens,
            int T, int U)
{
    const int b   = blockIdx.x;
    const int tid = threadIdx.x;

    const int tl = text_lens[b];
    const int ml = mel_lens[b];
    const int S  = 2 * tl;              // final state index

    __shared__ float sa[2][2 * TPB + 2];   // +2 front pad (NEG)
    __shared__ float sfin[2];

    for (int k = tid; k < 2 * TPB + 2; k += TPB) {
        sa[0][k] = (k == 2) ? 0.0f : NEGF;  // state 0 = log(1) = 0
        sa[1][k] = NEGF;                     // pads of buf 1 stay NEG
    }
    __syncthreads();

    const float* xb  = attn + (size_t)b * (size_t)T * (size_t)U;
    const float* lzp = g_logZ + (size_t)b * (size_t)T;

    const int  s0  = tid;
    const int  s1  = tid + TPB;
    const bool odd = (tid & 1) != 0;          // s0 and s1 share parity
    const int  xc0 = ((tid + 1) >> 1) - 1;    // x col for odd s0 (0-based)
    const int  xc1 = xc0 + 128;               // x col for odd s1
    // validity: odd state s valid iff s <= S-1 (label <= tl); even iff s <= S
    const bool v0 = odd ? (s0 <= S - 1) : (s0 <= S);
    const bool v1 = odd ? (s1 <= S - 1) : (s1 <= S);

    // prefetch t = 0
    float xA = 0.0f, xB = 0.0f;
    if (odd) {
        if (v0) xA = __ldg(&xb[xc0]);
        if (v1) xB = __ldg(&xb[xc1]);
    }
    float lzt = __ldg(&lzp[0]);

    for (int t = 0; t < ml; ++t) {
        const int p = t & 1;

        const float lp0 = v0 ? ((odd ? xA : -1.0f) - lzt) : NEGF;
        const float lp1 = v1 ? ((odd ? xB : -1.0f) - lzt) : NEGF;

        // prefetch next row
        if (t + 1 < ml) {
            if (odd) {
                const float* row = xb + (size_t)(t + 1) * (size_t)U;
                if (v0) xA = __ldg(&row[xc0]);
                if (v1) xB = __ldg(&row[xc1]);
            }
            lzt = __ldg(&lzp[t + 1]);
        }

        const float* ao = sa[p] + 2;
        float n0, n1;
        {
            float a1 = ao[s0], a2 = ao[s0 - 1];
            float m  = fmaxf(a1, a2);
            float s;
            if (odd) {
                float a3 = ao[s0 - 2];
                m = fmaxf(m, a3);
                s = __expf(a1 - m) + __expf(a2 - m) + __expf(a3 - m);
            } else {
                s = __expf(a1 - m) + __expf(a2 - m);
            }
            n0 = lp0 + (m + __logf(s));
        }
        {
            float a1 = ao[s1], a2 = ao[s1 - 1];
            float m  = fmaxf(a1, a2);
            float s;
            if (odd) {
                float a3 = ao[s1 - 2];
                m = fmaxf(m, a3);
                s = __expf(a1 - m) + __expf(a2 - m) + __expf(a3 - m);
            } else {
                s = __expf(a1 - m) + __expf(a2 - m);
            }
            n1 = lp1 + (m + __logf(s));
        }

        float* an = sa[1 - p] + 2;
        an[s0] = n0;
        an[s1] = n1;

        if (t == ml - 1) {
            if (s0 == S)     sfin[0] = n0;
            if (s1 == S)     sfin[0] = n1;
            if (s0 == S - 1) sfin[1] = n0;
            if (s1 == S - 1) sfin[1] = n1;
        }

        __syncthreads();   // single barrier per step (double buffer)
    }

    if (tid == 0) {
        float va = sfin[0], vb = sfin[1];
        float mm  = fmaxf(va, vb);
        float fin = mm + __logf(__expf(va - mm) + __expf(vb - mm));
        g_loss[b] = (fin < 0.5f * NEGF) ? 0.0f : -fin / (float)tl;
    }
}

__global__ void fsloss_reduce(float* __restrict__ out, int B)
{
    __shared__ float ws[2];
    float v = (threadIdx.x < B) ? g_loss[threadIdx.x] : 0.0f;
    #pragma unroll
    for (int off = 16; off; off >>= 1)
        v += __shfl_xor_sync(0xffffffffu, v, off);
    if ((threadIdx.x & 31) == 0) ws[threadIdx.x >> 5] = v;
    __syncthreads();
    if (threadIdx.x == 0) out[0] = (ws[0] + ws[1]) / (float)B;
}

extern "C" void kernel_launch(void* const* d_in, const int* in_sizes, int n_in,
                              void* d_out, int out_size)
{
    const float* attn = (const float*)d_in[0];
    const int*   tl   = (const int*)d_in[1];
    const int*   ml   = (const int*)d_in[2];
    int B = in_sizes[1];
    const int U = 250;
    int T = in_sizes[0] / (B * U);

    int rows    = B * T;
    int blocksA = (rows * 32 + TPB - 1) / TPB;
    fsloss_logz<<<blocksA, TPB>>>(attn, tl, B, T, U);
    fsloss_scan<<<B, TPB>>>(attn, tl, ml, T, U);
    fsloss_reduce<<<1, 64>>>((float*)d_out, B);
}

// round 4
// speedup vs baseline: 2.7058x; 2.7058x over previous
#include <cuda_runtime.h>
#include <math.h>
#include <stdint.h>

#define FULLM 0xffffffffu
#define BMAX 64
#define TMAX 1000
#define UPAD 256
#define EBLANK 0.36787944117144233f

// Scratch (allocation-free rule: __device__ globals).
__device__ float g_loss[BMAX];
__device__ float g_pblank[BMAX * TMAX];
__device__ float g_p[(size_t)BMAX * TMAX * UPAD];   // 64 MB

// ---------------------------------------------------------------------------
// Phase 1: p[b,t,u] = exp(x)/Z, pblank[b,t] = e^-1/Z,  Z = e^-1 + sum exp(x).
// One warp per (b,t) row.
// ---------------------------------------------------------------------------
__global__ void __launch_bounds__(256)
fsloss_prep(const float* __restrict__ attn, const int* __restrict__ text_lens,
            int B, int T, int U)
{
    __shared__ float se[8][UPAD];
    const int w = threadIdx.x >> 5, lane = threadIdx.x & 31;
    const int row = blockIdx.x * 8 + w;
    if (row >= B * T) return;
    const int b  = row / T;
    const int tl = text_lens[b];
    const float* x = attn + (size_t)row * U;

    float s = 0.f;
    #pragma unroll
    for (int k = 0; k < 8; ++k) {
        int u = lane + 32 * k;
        float e = 0.f;
        if (u < tl) e = __expf(__ldg(&x[u]));
        se[w][u] = e;
        s += e;
    }
    #pragma unroll
    for (int off = 16; off; off >>= 1) s += __shfl_xor_sync(FULLM, s, off);
    const float rinv = 1.0f / (s + EBLANK);
    __syncwarp();

    float4* dst = (float4*)(g_p + (size_t)row * UPAD);
    const float4* src = (const float4*)se[w];
    #pragma unroll
    for (int j = 0; j < 2; ++j) {
        float4 v = src[lane * 2 + j];
        v.x *= rinv; v.y *= rinv; v.z *= rinv; v.w *= rinv;
        dst[lane * 2 + j] = v;
    }
    if (lane == 0) g_pblank[row] = EBLANK * rinv;
}

// ---------------------------------------------------------------------------
// Phase 2: one WARP per batch element. 512 states in registers (16/lane).
// Linear-domain recursion with PER-LANE power-of-2 exponent tracking
// (blocked floating point): each lane renorms its 16 states every 4 steps,
// cross-lane transfer rescaled by f = 2^(G_{l-1} - G_l). Zero lanes adopt
// the left neighbor's exponent so arriving mass is representable.
// ---------------------------------------------------------------------------
__device__ __forceinline__ void fs_step(float a[16], float4 q0, float4 q1,
                                        float pbt, float f)
{
    float am1 = __shfl_up_sync(FULLM, a[15], 1) * f;   // lane0: f=0 -> 0
    const float p[8] = {q0.x, q0.y, q0.z, q0.w, q1.x, q1.y, q1.z, q1.w};
    float prev = am1;
    #pragma unroll
    for (int k = 0; k < 8; ++k) {
        float e  = a[2*k] + prev;        // a[s] + a[s-1]
        float so = a[2*k+1] + e;         // a[s+1] + a[s] + a[s-1]
        prev = a[2*k+1];
        a[2*k]   = pbt  * e;
        a[2*k+1] = p[k] * so;
    }
}

#define FS_RENORM()                                                           \
    do {                                                                      \
        float m = a[0];                                                       \
        _Pragma("unroll")                                                     \
        for (int j = 1; j < 16; ++j) m = fmaxf(m, a[j]);                      \
        bool nz = (m > 0.f);                                                  \
        if (nz) {                                                             \
            int Ee = (int)((__float_as_uint(m) >> 23) & 255u);                \
            float sc = __uint_as_float((unsigned)(254 - Ee) << 23);           \
            _Pragma("unroll")                                                 \
            for (int j = 0; j < 16; ++j) a[j] *= sc;                          \
            G += Ee - 127;                                                    \
        }                                                                     \
        int Gup = __shfl_up_sync(FULLM, G, 1);                                \
        if (!nz && lane > 0) G = Gup;                                         \
        Gup = __shfl_up_sync(FULLM, G, 1);                                    \
        int D = Gup - G;                                                      \
        if (D > 127) D = 127;                                                 \
        f = (lane == 0 || D < -126) ? 0.f                                     \
            : __uint_as_float((unsigned)(D + 127) << 23);                     \
    } while (0)

#define FS_CAPTURE()                                                          \
    do {                                                                      \
        _Pragma("unroll")                                                     \
        for (int j = 0; j < 16; ++j) {                                        \
            int s = lane * 16 + j;                                            \
            if (s == S || s == S - 1) fincap += a[j];                         \
        }                                                                     \
        Gcap = G;                                                             \
    } while (0)

__global__ void __launch_bounds__(32)
fsloss_scan(const int* __restrict__ text_lens, const int* __restrict__ mel_lens,
            int T)
{
    const int b = blockIdx.x, lane = threadIdx.x;
    const int tl = text_lens[b], ml = mel_lens[b];
    const int S = 2 * tl, mlm1 = ml - 1;
    const float4* P  = (const float4*)(g_p + (size_t)b * T * UPAD);
    const float4* PB = (const float4*)(g_pblank + (size_t)b * T);
    const int i0 = 2 * lane, i1 = 2 * lane + 1;

    float a[16];
    #pragma unroll
    for (int j = 0; j < 16; ++j) a[j] = 0.f;
    if (lane == 0) a[0] = 1.f;

    int   G = 0, Gcap = 0;
    float fincap = 0.f;
    float f = (lane == 0) ? 0.f : 1.f;

    float4 A0[4], A1[4], B0[4], B1[4];
    float4 pbA = PB[0], pbB = PB[1];
    #pragma unroll
    for (int r = 0; r < 4; ++r) { A0[r] = P[(size_t)r * 64 + i0];
                                  A1[r] = P[(size_t)r * 64 + i1]; }
    #pragma unroll
    for (int r = 0; r < 4; ++r) { B0[r] = P[(size_t)(r + 4) * 64 + i0];
                                  B1[r] = P[(size_t)(r + 4) * 64 + i1]; }

    const int mlpad = (ml + 7) & ~7;
    for (int t = 0; t < mlpad; t += 8) {
        #pragma unroll
        for (int r = 0; r < 4; ++r) {
            float pbt = (r == 0) ? pbA.x : (r == 1) ? pbA.y : (r == 2) ? pbA.z : pbA.w;
            fs_step(a, A0[r], A1[r], pbt, f);
            if (t + r == mlm1) FS_CAPTURE();
        }
        {   // prefetch rows t+8..t+11 (issue before renorm to overlap)
            int rb = t + 8; if (rb > T - 4) rb = T - 4;
            #pragma unroll
            for (int r = 0; r < 4; ++r) { A0[r] = P[(size_t)(rb + r) * 64 + i0];
                                          A1[r] = P[(size_t)(rb + r) * 64 + i1]; }
            pbA = PB[rb >> 2];
        }
        FS_RENORM();
        #pragma unroll
        for (int r = 0; r < 4; ++r) {
            float pbt = (r == 0) ? pbB.x : (r == 1) ? pbB.y : (r == 2) ? pbB.z : pbB.w;
            fs_step(a, B0[r], B1[r], pbt, f);
            if (t + 4 + r == mlm1) FS_CAPTURE();
        }
        {   // prefetch rows t+12..t+15
            int rb = t + 12; if (rb > T - 4) rb = T - 4;
            #pragma unroll
            for (int r = 0; r < 4; ++r) { B0[r] = P[(size_t)(rb + r) * 64 + i0];
                                          B1[r] = P[(size_t)(rb + r) * 64 + i1]; }
            pbB = PB[rb >> 2];
        }
        FS_RENORM();
    }

    // combine (at most 2 lanes hold fin terms, each with its own exponent)
    double lv = (fincap > 0.f)
        ? (log((double)fincap) + (double)Gcap * 0.6931471805599453)
        : -1e300;
    double mx = lv;
    #pragma unroll
    for (int off = 16; off; off >>= 1) {
        double o = __shfl_xor_sync(FULLM, mx, off);
        mx = fmax(mx, o);
    }
    double ex = (lv > -1e299) ? exp(lv - mx) : 0.0;
    #pragma unroll
    for (int off = 16; off; off >>= 1)
        ex += __shfl_xor_sync(FULLM, ex, off);
    if (lane == 0) {
        float loss = 0.f;
        if (mx > -1e299) {
            double fin = mx + log(ex);
            loss = (float)(-fin / (double)tl);
        }
        g_loss[b] = loss;
    }
}

__global__ void fsloss_reduce(float* __restrict__ out, int B)
{
    __shared__ float ws[2];
    float v = (threadIdx.x < B) ? g_loss[threadIdx.x] : 0.0f;
    #pragma unroll
    for (int off = 16; off; off >>= 1)
        v += __shfl_xor_sync(FULLM, v, off);
    if ((threadIdx.x & 31) == 0) ws[threadIdx.x >> 5] = v;
    __syncthreads();
    if (threadIdx.x == 0) out[0] = (ws[0] + ws[1]) / (float)B;
}

extern "C" void kernel_launch(void* const* d_in, const int* in_sizes, int n_in,
                              void* d_out, int out_size)
{
    const float* attn = (const float*)d_in[0];
    const int*   tl   = (const int*)d_in[1];
    const int*   ml   = (const int*)d_in[2];
    int B = in_sizes[1];
    const int U = 250;
    int T = in_sizes[0] / (B * U);

    int rows = B * T;
    fsloss_prep<<<(rows + 7) / 8, 256>>>(attn, tl, B, T, U);
    fsloss_scan<<<B, 32>>>(tl, ml, T);
    fsloss_reduce<<<1, 64>>>((float*)d_out, B);
}

// round 5
// speedup vs baseline: 2.9300x; 1.0829x over previous
#include <cuda_runtime.h>
#include <math.h>
#include <stdint.h>

#define FULLM 0xffffffffu
#define BMAX 64
#define TMAX 1000
#define UPAD 256
#define EBLANK 0.36787944117144233f

// Scratch (allocation-free rule: __device__ globals).
__device__ float g_loss[BMAX];
__device__ float g_pblank[BMAX * TMAX];
__device__ float g_p[(size_t)BMAX * TMAX * UPAD];   // 64 MB

// ---------------------------------------------------------------------------
// Phase 1: p[b,t,u] = exp(x)/Z, pblank[b,t] = e^-1/Z,  Z = e^-1 + sum exp(x).
// One warp per (b,t) row; lane handles 8 contiguous cols; no smem staging.
// attn rows are 1000 B apart -> 8-byte aligned -> float2 loads are legal.
// ---------------------------------------------------------------------------
__global__ void __launch_bounds__(256)
fsloss_prep(const float* __restrict__ attn, const int* __restrict__ text_lens,
            int B, int T, int U)
{
    const int gw   = (blockIdx.x * blockDim.x + threadIdx.x) >> 5;
    const int lane = threadIdx.x & 31;
    if (gw >= B * T) return;
    const int b  = gw / T;
    const int tl = text_lens[b];
    const int u0 = 8 * lane;

    const float2* x2 = (const float2*)(attn + (size_t)gw * U) + 4 * lane;
    float v[8];
    #pragma unroll
    for (int j = 0; j < 4; ++j) {
        float2 d = make_float2(0.f, 0.f);
        if (u0 + 2 * j + 1 < U) d = __ldg(&x2[j]);   // lane31 loads only j=0
        v[2 * j]     = d.x;
        v[2 * j + 1] = d.y;
    }
    float s = 0.f;
    #pragma unroll
    for (int k = 0; k < 8; ++k) {
        float e = (u0 + k < tl) ? __expf(v[k]) : 0.f;
        v[k] = e;
        s += e;
    }
    #pragma unroll
    for (int off = 16; off; off >>= 1) s += __shfl_xor_sync(FULLM, s, off);
    const float rinv = __fdividef(1.0f, s + EBLANK);
    #pragma unroll
    for (int k = 0; k < 8; ++k) v[k] *= rinv;

    float4* dst = (float4*)(g_p + (size_t)gw * UPAD + u0);
    dst[0] = make_float4(v[0], v[1], v[2], v[3]);
    dst[1] = make_float4(v[4], v[5], v[6], v[7]);
    if (lane == 0) g_pblank[gw] = EBLANK * rinv;
}

// ---------------------------------------------------------------------------
// Phase 2: one WARP per batch element. 512 states in registers (16/lane).
// Linear-domain recursion with per-lane power-of-2 exponent tracking.
// Main loop: branch-free 8-step blocks; capture handled in a short tail.
// ---------------------------------------------------------------------------
__device__ __forceinline__ void fs_step(float a[16], float4 q0, float4 q1,
                                        float pbt, float f)
{
    float am1 = __shfl_up_sync(FULLM, a[15], 1) * f;   // lane0: f=0 -> 0
    const float p[8] = {q0.x, q0.y, q0.z, q0.w, q1.x, q1.y, q1.z, q1.w};
    float prev = am1;
    #pragma unroll
    for (int k = 0; k < 8; ++k) {
        float e  = a[2*k] + prev;        // a[s] + a[s-1]
        float so = a[2*k+1] + e;         // a[s+1] + a[s] + a[s-1]
        prev = a[2*k+1];
        a[2*k]   = pbt  * e;
        a[2*k+1] = p[k] * so;
    }
}

#define FS_RENORM()                                                           \
    do {                                                                      \
        float m = a[0];                                                       \
        _Pragma("unroll")                                                     \
        for (int j = 1; j < 16; ++j) m = fmaxf(m, a[j]);                      \
        bool nz = (m > 0.f);                                                  \
        if (nz) {                                                             \
            int Ee = (int)((__float_as_uint(m) >> 23) & 255u);                \
            float sc = __uint_as_float((unsigned)(254 - Ee) << 23);           \
            _Pragma("unroll")                                                 \
            for (int j = 0; j < 16; ++j) a[j] *= sc;                          \
            G += Ee - 127;                                                    \
        }                                                                     \
        int Gup = __shfl_up_sync(FULLM, G, 1);                                \
        if (!nz && lane > 0) G = Gup;                                         \
        Gup = __shfl_up_sync(FULLM, G, 1);                                    \
        int D = Gup - G;                                                      \
        if (D > 127) D = 127;                                                 \
        f = (lane == 0 || D < -126) ? 0.f                                     \
            : __uint_as_float((unsigned)(D + 127) << 23);                     \
    } while (0)

#define FS_CAPTURE()                                                          \
    do {                                                                      \
        _Pragma("unroll")                                                     \
        for (int j = 0; j < 16; ++j) {                                        \
            int s = lane * 16 + j;                                            \
            fincap += (s == S || s == S - 1) ? a[j] : 0.f;                    \
        }                                                                     \
        Gcap = G;                                                             \
    } while (0)

__global__ void __launch_bounds__(32)
fsloss_scan(const int* __restrict__ text_lens, const int* __restrict__ mel_lens,
            int T)
{
    const int b = blockIdx.x, lane = threadIdx.x;
    const int tl = text_lens[b], ml = mel_lens[b];
    const int S = 2 * tl, mlm1 = ml - 1;
    const float4* P  = (const float4*)(g_p + (size_t)b * T * UPAD);
    const float4* PB = (const float4*)(g_pblank + (size_t)b * T);
    const float4* p0 = P + 2 * lane;
    const float4* p1 = P + 2 * lane + 1;

    float a[16];
    #pragma unroll
    for (int j = 0; j < 16; ++j) a[j] = 0.f;
    if (lane == 0) a[0] = 1.f;

    int   G = 0, Gcap = 0;
    float fincap = 0.f;
    float f = (lane == 0) ? 0.f : 1.f;

    float4 A0[4], A1[4], B0[4], B1[4];
    float4 pbA = PB[0], pbB = PB[1];
    #pragma unroll
    for (int r = 0; r < 4; ++r) { A0[r] = p0[r * 64];       A1[r] = p1[r * 64]; }
    #pragma unroll
    for (int r = 0; r < 4; ++r) { B0[r] = p0[(r + 4) * 64]; B1[r] = p1[(r + 4) * 64]; }

    const int full = mlm1 >> 3;           // complete 8-step blocks before capture
    const float4* q0 = p0 + 512;          // row 8
    const float4* q1 = p1 + 512;
    const float4* pbq = PB + 2;

    for (int blk = 0; blk < full; ++blk) {
        fs_step(a, A0[0], A1[0], pbA.x, f);
        fs_step(a, A0[1], A1[1], pbA.y, f);
        fs_step(a, A0[2], A1[2], pbA.z, f);
        fs_step(a, A0[3], A1[3], pbA.w, f);
        #pragma unroll
        for (int r = 0; r < 4; ++r) { A0[r] = q0[r * 64]; A1[r] = q1[r * 64]; }
        pbA = pbq[0];
        FS_RENORM();
        fs_step(a, B0[0], B1[0], pbB.x, f);
        fs_step(a, B0[1], B1[1], pbB.y, f);
        fs_step(a, B0[2], B1[2], pbB.z, f);
        fs_step(a, B0[3], B1[3], pbB.w, f);
        #pragma unroll
        for (int r = 0; r < 4; ++r) { B0[r] = q0[(r + 4) * 64]; B1[r] = q1[(r + 4) * 64]; }
        pbB = pbq[1];
        FS_RENORM();
        q0 += 512; q1 += 512; pbq += 2;
    }

    // tail: steps 8*full .. mlm1 (1..8 steps); rows already in A/B buffers.
    {
        const int rem = mlm1 - 8 * full;  // 0..7
        #pragma unroll
        for (int r = 0; r < 8; ++r) {
            float4 t0  = (r < 4) ? A0[r & 3] : B0[r & 3];
            float4 t1  = (r < 4) ? A1[r & 3] : B1[r & 3];
            float  pbt = (r == 0) ? pbA.x : (r == 1) ? pbA.y : (r == 2) ? pbA.z :
                         (r == 3) ? pbA.w : (r == 4) ? pbB.x : (r == 5) ? pbB.y :
                         (r == 6) ? pbB.z : pbB.w;
            fs_step(a, t0, t1, pbt, f);
            if (r == rem) { FS_CAPTURE(); break; }
            if (r == 3) FS_RENORM();
        }
    }

    // combine (at most 2 lanes hold fin terms, each with its own exponent)
    double lv = (fincap > 0.f)
        ? (log((double)fincap) + (double)Gcap * 0.6931471805599453)
        : -1e300;
    double mx = lv;
    #pragma unroll
    for (int off = 16; off; off >>= 1) {
        double o = __shfl_xor_sync(FULLM, mx, off);
        mx = fmax(mx, o);
    }
    double ex = (lv > -1e299) ? exp(lv - mx) : 0.0;
    #pragma unroll
    for (int off = 16; off; off >>= 1)
        ex += __shfl_xor_sync(FULLM, ex, off);
    if (lane == 0) {
        float loss = 0.f;
        if (mx > -1e299) {
            double fin = mx + log(ex);
            loss = (float)(-fin / (double)tl);
        }
        g_loss[b] = loss;
    }
}

__global__ void fsloss_reduce(float* __restrict__ out, int B)
{
    __shared__ float ws[2];
    float v = (threadIdx.x < B) ? g_loss[threadIdx.x] : 0.0f;
    #pragma unroll
    for (int off = 16; off; off >>= 1)
        v += __shfl_xor_sync(FULLM, v, off);
    if ((threadIdx.x & 31) == 0) ws[threadIdx.x >> 5] = v;
    __syncthreads();
    if (threadIdx.x == 0) out[0] = (ws[0] + ws[1]) / (float)B;
}

extern "C" void kernel_launch(void* const* d_in, const int* in_sizes, int n_in,
                              void* d_out, int out_size)
{
    const float* attn = (const float*)d_in[0];
    const int*   tl   = (const int*)d_in[1];
    const int*   ml   = (const int*)d_in[2];
    int B = in_sizes[1];
    const int U = 250;
    int T = in_sizes[0] / (B * U);

    int rows = B * T;
    fsloss_prep<<<(rows * 32 + 255) / 256, 256>>>(attn, tl, B, T, U);
    fsloss_scan<<<B, 32>>>(tl, ml, T);
    fsloss_reduce<<<1, 64>>>((float*)d_out, B);
}